// round 14
// baseline (speedup 1.0000x reference)
#include <cuda_runtime.h>
#include <cuda_fp16.h>
#include <math.h>
#include <stdint.h>

#define EPSV 1e-5f
constexpr int Bb=8, Cc=64, Tt=1000, Ff=64, Hh=4, HSs=4, CVv=16;
constexpr int Dd=HSs*Ff, DV=CVv*Ff, HB=Hh*Bb, Tp=1024;

// zero-initialized device scratch (padded tails stay zero forever)
__device__ __half g_Qh [HB * Tp * Dd];   // [t][d]
__device__ __half g_Kh [HB * Tp * Dd];   // [s][d]
__device__ __half g_Vh [HB * Tp * DV];   // [s][n]
__device__ __half g_Vth[HB * DV * Tp];   // [n][s]
__device__ float  g_P  [HB * Tp * Tp];   // scores [t][s] float
__device__ __half g_Ph [HB * Tp * Tp];   // probs  [t][s] half (pads stay 0)
__device__ float  g_A  [HB * Tp * DV];   // [t][n]

// ---------------- helpers ----------------
__device__ __forceinline__ uint32_t smem_u32(const void* p) {
    uint32_t a;
    asm("{ .reg .u64 t; cvta.to.shared.u64 t, %1; cvt.u32.u64 %0, t; }" : "=r"(a) : "l"(p));
    return a;
}
#define LDM4(r0,r1,r2,r3,addr) \
    asm volatile("ldmatrix.sync.aligned.m8n8.x4.shared.b16 {%0,%1,%2,%3}, [%4];" \
        : "=r"(r0),"=r"(r1),"=r"(r2),"=r"(r3) : "r"(addr))
#define CPASYNC16(sdst, gsrc) \
    asm volatile("cp.async.cg.shared.global [%0], [%1], 16;" :: "r"(sdst), "l"(gsrc))
#define CPCOMMIT() asm volatile("cp.async.commit_group;")
#define CPWAIT2()  asm volatile("cp.async.wait_group 2;")

__device__ __forceinline__ void mma_f16(float* c, const uint32_t* a, const uint32_t* b) {
    asm volatile(
        "mma.sync.aligned.m16n8k16.row.col.f32.f16.f16.f32 "
        "{%0,%1,%2,%3}, {%4,%5,%6,%7}, {%8,%9}, {%0,%1,%2,%3};"
        : "+f"(c[0]), "+f"(c[1]), "+f"(c[2]), "+f"(c[3])
        : "r"(a[0]), "r"(a[1]), "r"(a[2]), "r"(a[3]), "r"(b[0]), "r"(b[1]));
}
__device__ __forceinline__ void group_reduce64(float& s, float& ss, int tid,
                                               float* reds, float* redss) {
    #pragma unroll
    for (int o = 16; o > 0; o >>= 1) {
        s  += __shfl_xor_sync(0xffffffffu, s,  o);
        ss += __shfl_xor_sync(0xffffffffu, ss, o);
    }
    if ((tid & 31) == 0) { reds[tid >> 5] = s; redss[tid >> 5] = ss; }
    __syncthreads();
    int h = tid >> 6;
    s  = reds[2 * h]  + reds[2 * h + 1];
    ss = redss[2 * h] + redss[2 * h + 1];
    __syncthreads();
}

// ---------------- Kernel 1: QKV proj + PReLU + ChanFreqNorm (half out) -----
__global__ void __launch_bounds__(256) qkv_kernel(
    const float* __restrict__ x,
    const float* __restrict__ qw, const float* __restrict__ qb,
    const float* __restrict__ qa, const float* __restrict__ qg, const float* __restrict__ qbe,
    const float* __restrict__ kw, const float* __restrict__ kb,
    const float* __restrict__ ka, const float* __restrict__ kg, const float* __restrict__ kbe,
    const float* __restrict__ vw, const float* __restrict__ vb,
    const float* __restrict__ va, const float* __restrict__ vg, const float* __restrict__ vbe)
{
    __shared__ float xs[Cc * Ff], qws[Hh*HSs*Cc], kws[Hh*HSs*Cc], vws[Hh*CVv*Cc];
    __shared__ float reds[8], redss[8];
    int bid = blockIdx.x, b = bid / Tt, t = bid % Tt, tid = threadIdx.x;

    for (int i = tid; i < Cc * Ff; i += 256) {
        int c = i >> 6, f = i & 63;
        xs[i] = x[(((size_t)b * Cc + c) * Tt + t) * Ff + f];
    }
    for (int i = tid; i < Hh*HSs*Cc; i += 256) { qws[i] = qw[i]; kws[i] = kw[i]; }
    for (int i = tid; i < Hh*CVv*Cc; i += 256) vws[i] = vw[i];
    __syncthreads();

    int h = tid >> 6, f = tid & 63;
    float qv[HSs], kv[HSs], vv[CVv];
    #pragma unroll
    for (int i = 0; i < HSs; i++) { qv[i] = 0.f; kv[i] = 0.f; }
    #pragma unroll
    for (int i = 0; i < CVv; i++) vv[i] = 0.f;

    for (int c = 0; c < Cc; c++) {
        float xv = xs[c * Ff + f];
        #pragma unroll
        for (int i = 0; i < HSs; i++) {
            qv[i] = fmaf(qws[(h*HSs+i)*Cc + c], xv, qv[i]);
            kv[i] = fmaf(kws[(h*HSs+i)*Cc + c], xv, kv[i]);
        }
        #pragma unroll
        for (int i = 0; i < CVv; i++)
            vv[i] = fmaf(vws[(h*CVv+i)*Cc + c], xv, vv[i]);
    }
    int hb = h * Bb + b;
    { // Q
        float al = qa[h], s = 0.f, ss = 0.f;
        #pragma unroll
        for (int i = 0; i < HSs; i++) {
            float y = qv[i] + qb[h*HSs+i]; y = y > 0.f ? y : al * y;
            qv[i] = y; s += y; ss += y * y;
        }
        group_reduce64(s, ss, tid, reds, redss);
        float mu = s / (HSs*Ff), var = ss / (HSs*Ff) - mu*mu;
        float inv = 1.f / (sqrtf(fmaxf(var, 0.f)) + EPSV);
        size_t base = ((size_t)hb * Tp + t) * Dd;
        #pragma unroll
        for (int i = 0; i < HSs; i++) {
            int gi = (h*HSs+i)*Ff + f;
            g_Qh[base + i*Ff + f] = __float2half((qv[i]-mu)*inv*qg[gi] + qbe[gi]);
        }
    }
    { // K
        float al = ka[h], s = 0.f, ss = 0.f;
        #pragma unroll
        for (int i = 0; i < HSs; i++) {
            float y = kv[i] + kb[h*HSs+i]; y = y > 0.f ? y : al * y;
            kv[i] = y; s += y; ss += y * y;
        }
        group_reduce64(s, ss, tid, reds, redss);
        float mu = s / (HSs*Ff), var = ss / (HSs*Ff) - mu*mu;
        float inv = 1.f / (sqrtf(fmaxf(var, 0.f)) + EPSV);
        size_t base = ((size_t)hb * Tp + t) * Dd;
        #pragma unroll
        for (int i = 0; i < HSs; i++) {
            int gi = (h*HSs+i)*Ff + f;
            g_Kh[base + i*Ff + f] = __float2half((kv[i]-mu)*inv*kg[gi] + kbe[gi]);
        }
    }
    { // V
        float al = va[h], s = 0.f, ss = 0.f;
        #pragma unroll
        for (int i = 0; i < CVv; i++) {
            float y = vv[i] + vb[h*CVv+i]; y = y > 0.f ? y : al * y;
            vv[i] = y; s += y; ss += y * y;
        }
        group_reduce64(s, ss, tid, reds, redss);
        float mu = s / (CVv*Ff), var = ss / (CVv*Ff) - mu*mu;
        float inv = 1.f / (sqrtf(fmaxf(var, 0.f)) + EPSV);
        size_t base = ((size_t)hb * Tp + t) * DV;
        #pragma unroll
        for (int i = 0; i < CVv; i++) {
            int gi = (h*CVv+i)*Ff + f;
            g_Vh[base + i*Ff + f] = __float2half((vv[i]-mu)*inv*vg[gi] + vbe[gi]);
        }
    }
}

// ---------------- Kernel 2: transpose Vh [s][n] -> Vth [n][s] (half) -------
__global__ void __launch_bounds__(256) transV_kernel()
{
    __shared__ __half tile[32][34];
    int hb = blockIdx.z, t0 = blockIdx.y * 32, n0 = blockIdx.x * 32;
    int tx = threadIdx.x & 31, ty = threadIdx.x >> 5;
    const __half* __restrict__ src = g_Vh  + (size_t)hb * Tp * DV;
    __half* __restrict__       dst = g_Vth + (size_t)hb * DV * Tp;
    #pragma unroll
    for (int j = 0; j < 4; j++)
        tile[ty + 8*j][tx] = src[(size_t)(t0 + ty + 8*j) * DV + n0 + tx];
    __syncthreads();
    #pragma unroll
    for (int j = 0; j < 4; j++)
        dst[(size_t)(n0 + ty + 8*j) * Tp + t0 + tx] = tile[tx][ty + 8*j];
}

// ---------------- fp16 GEMM 128x128: C[m][n] = sum_k A[m][k]*B[n][k] -------
// Round-9-proven layout/fragments; pipeline deepened 3 -> 4 stages.
// smem row stride 40 halves (80B) -> conflict-free ldmatrix, zero swizzle ALU.
template<int LDA, int LDB, int KT>
__device__ __forceinline__ void gemm_h16(const __half* __restrict__ Ag,
                                         const __half* __restrict__ Bg,
                                         float* __restrict__ Cg, float scale)
{
    extern __shared__ __half sh[];
    const int RS  = 40;          // halves per smem row
    const int STG = 128 * RS;    // halves per stage per operand
    __half* sA = sh;             // [4][STG]
    __half* sB = sh + 4 * STG;

    int tid = threadIdx.x, lane = tid & 31, w = tid >> 5;
    int m0 = blockIdx.y * 128, n0 = blockIdx.x * 128;
    int wm = (w & 1) * 64, wn = (w >> 1) * 32;
    int r = lane >> 2, cq = lane & 3;
    int g = lane >> 3, rw = lane & 7;

    uint32_t sA_u = smem_u32(sA), sB_u = smem_u32(sB);

    // cp.async: thread -> row lr (0..127), 32B (two 16B chunks) at c0
    int lr = tid >> 1, c0 = (tid & 1) * 16;       // c0 in halves
    uint32_t sAd = sA_u + (uint32_t)(lr * RS + c0) * 2;
    uint32_t sBd = sB_u + (uint32_t)(lr * RS + c0) * 2;
    const __half* Asrc = Ag + (size_t)(m0 + lr) * LDA + c0;
    const __half* Bsrc = Bg + (size_t)(n0 + lr) * LDB + c0;

    auto LOAD = [&](int kt) {
        uint32_t so = (uint32_t)(kt & 3) * STG * 2;
        CPASYNC16(sAd + so,      Asrc + kt * 32);
        CPASYNC16(sAd + so + 16, Asrc + kt * 32 + 8);
        CPASYNC16(sBd + so,      Bsrc + kt * 32);
        CPASYNC16(sBd + so + 16, Bsrc + kt * 32 + 8);
        CPCOMMIT();
    };

    // ldmatrix lane offset (bytes): row = (g&1)*8 + rw, k-chunk = (g>>1)
    uint32_t lofs = (uint32_t)(((g & 1) * 8 + rw) * (RS * 2) + (g >> 1) * 16);

    float acc[4][4][4];
    #pragma unroll
    for (int i = 0; i < 4; i++)
        #pragma unroll
        for (int j = 0; j < 4; j++)
            #pragma unroll
            for (int q = 0; q < 4; q++) acc[i][j][q] = 0.f;

    LOAD(0); LOAD(1); LOAD(2);

    for (int kt = 0; kt < KT; kt++) {
        CPWAIT2();
        __syncthreads();
        uint32_t so = (uint32_t)(kt & 3) * STG * 2;
        uint32_t bufA = sA_u + so + lofs;
        uint32_t bufB = sB_u + so + lofs;
        #pragma unroll
        for (int ks = 0; ks < 2; ks++) {
            uint32_t af[4][4], bf[4][2];
            #pragma unroll
            for (int mi = 0; mi < 4; mi++)
                LDM4(af[mi][0], af[mi][1], af[mi][2], af[mi][3],
                     bufA + (uint32_t)((wm + mi * 16) * (RS * 2) + ks * 32));
            #pragma unroll
            for (int nj = 0; nj < 2; nj++) {
                uint32_t q0, q1, q2, q3;
                LDM4(q0, q1, q2, q3,
                     bufB + (uint32_t)((wn + nj * 16) * (RS * 2) + ks * 32));
                bf[nj*2][0]   = q0;  bf[nj*2][1]   = q2;
                bf[nj*2+1][0] = q1;  bf[nj*2+1][1] = q3;
            }
            #pragma unroll
            for (int mi = 0; mi < 4; mi++)
                #pragma unroll
                for (int ni = 0; ni < 4; ni++)
                    mma_f16(acc[mi][ni], af[mi], bf[ni]);
        }
        // commit every iteration so wait_group 2 drains the tail correctly:
        // at top of iter kt, 3+kt groups committed -> >= kt+1 complete.
        if (kt + 3 < KT) LOAD(kt + 3);
        else CPCOMMIT();
    }

    #pragma unroll
    for (int mi = 0; mi < 4; mi++)
        #pragma unroll
        for (int ni = 0; ni < 4; ni++) {
            int row = m0 + wm + mi * 16 + r;
            int col = n0 + wn + ni * 8 + 2 * cq;
            *(float2*)&Cg[(size_t)row * 1024 + col] =
                make_float2(acc[mi][ni][0] * scale, acc[mi][ni][1] * scale);
            *(float2*)&Cg[(size_t)(row + 8) * 1024 + col] =
                make_float2(acc[mi][ni][2] * scale, acc[mi][ni][3] * scale);
        }
}

// S[t][s] = sum_d Q[t][d] * K[s][d], scaled
__global__ void __launch_bounds__(256, 2) gemm_qk_h()
{
    int hb = blockIdx.z;
    gemm_h16<Dd, Dd, Dd/32>(g_Qh + (size_t)hb * Tp * Dd,
                            g_Kh + (size_t)hb * Tp * Dd,
                            g_P  + (size_t)hb * Tp * Tp, 0.0625f);
}
// A[t][n] = sum_s P[t][s] * Vt[n][s]
__global__ void __launch_bounds__(256, 2) gemm_pv_h()
{
    int hb = blockIdx.z;
    gemm_h16<Tp, Tp, Tp/32>(g_Ph  + (size_t)hb * Tp * Tp,
                            g_Vth + (size_t)hb * DV * Tp,
                            g_A   + (size_t)hb * Tp * DV, 1.0f);
}

// ---------------- Kernel 3: row softmax S(float) -> P(half), zero pads -----
__global__ void __launch_bounds__(256) softmax_kernel()
{
    __shared__ float red[8];
    int hb = blockIdx.x / Tt, mrow = blockIdx.x % Tt;
    const float* __restrict__ p = g_P  + ((size_t)hb * Tp + mrow) * Tp;
    __half* __restrict__      o = g_Ph + ((size_t)hb * Tp + mrow) * Tp;
    int tid = threadIdx.x;

    float v[4];
    int cnt = 0;
    float m = -1e30f;
    for (int i = tid; i < Tt; i += 256) { v[cnt] = p[i]; m = fmaxf(m, v[cnt]); cnt++; }
    #pragma unroll
    for (int off = 16; off > 0; off >>= 1) m = fmaxf(m, __shfl_xor_sync(0xffffffffu, m, off));
    if ((tid & 31) == 0) red[tid >> 5] = m;
    __syncthreads();
    m = red[0];
    #pragma unroll
    for (int wv = 1; wv < 8; wv++) m = fmaxf(m, red[wv]);
    __syncthreads();

    float s = 0.f;
    for (int i = 0; i < cnt; i++) { v[i] = __expf(v[i] - m); s += v[i]; }
    #pragma unroll
    for (int off = 16; off > 0; off >>= 1) s += __shfl_xor_sync(0xffffffffu, s, off);
    if ((tid & 31) == 0) red[tid >> 5] = s;
    __syncthreads();
    s = 0.f;
    #pragma unroll
    for (int wv = 0; wv < 8; wv++) s += red[wv];

    float inv = 1.f / s;
    cnt = 0;
    for (int i = tid; i < Tt; i += 256) { o[i] = __float2half(v[cnt] * inv); cnt++; }
    for (int i = Tt + tid; i < Tp; i += 256) o[i] = __float2half(0.f);
}

// ---------------- Kernel 5: out proj + PReLU + ChanFreqNorm + residual -----
__global__ void __launch_bounds__(256) out_kernel(
    const float* __restrict__ x,
    const float* __restrict__ lw, const float* __restrict__ lb,
    const float* __restrict__ la, const float* __restrict__ lg,
    const float* __restrict__ lbe, float* __restrict__ out)
{
    __shared__ float xs[Cc * Ff], lws[Cc * Cc];
    __shared__ float reds[8], redss[8];
    int bid = blockIdx.x, b = bid / Tt, t = bid % Tt, tid = threadIdx.x;

    for (int h = 0; h < Hh; h++) {
        size_t base = ((size_t)(h * Bb + b) * Tp + t) * DV;
        for (int i = tid; i < DV; i += 256) xs[h * DV + i] = g_A[base + i];
    }
    for (int i = tid; i < Cc * Cc; i += 256) lws[i] = lw[i];
    __syncthreads();

    int f = tid & 63, co = tid >> 6;
    float alpha = la[0];
    float yv[16];
    #pragma unroll
    for (int j = 0; j < 16; j++) yv[j] = lb[co * 16 + j];
    for (int ci = 0; ci < Cc; ci++) {
        float xv = xs[ci * Ff + f];
        #pragma unroll
        for (int j = 0; j < 16; j++)
            yv[j] = fmaf(lws[(co * 16 + j) * Cc + ci], xv, yv[j]);
    }
    float s = 0.f, ss = 0.f;
    #pragma unroll
    for (int j = 0; j < 16; j++) {
        float y = yv[j]; y = y > 0.f ? y : alpha * y;
        yv[j] = y; s += y; ss += y * y;
    }
    #pragma unroll
    for (int o = 16; o > 0; o >>= 1) {
        s  += __shfl_xor_sync(0xffffffffu, s,  o);
        ss += __shfl_xor_sync(0xffffffffu, ss, o);
    }
    if ((tid & 31) == 0) { reds[tid >> 5] = s; redss[tid >> 5] = ss; }
    __syncthreads();
    s = 0.f; ss = 0.f;
    #pragma unroll
    for (int wv = 0; wv < 8; wv++) { s += reds[wv]; ss += redss[wv]; }

    float mu  = s * (1.f / 4096.f);
    float var = ss * (1.f / 4096.f) - mu * mu;
    float inv = 1.f / (sqrtf(fmaxf(var, 0.f)) + EPSV);
    #pragma unroll
    for (int j = 0; j < 16; j++) {
        int c = co * 16 + j;
        size_t oi = (((size_t)b * Cc + c) * Tt + t) * Ff + f;
        out[oi] = (yv[j] - mu) * inv * lg[c * Ff + f] + lbe[c * Ff + f] + x[oi];
    }
}

// ---------------------------------------------------------------------------
extern "C" void kernel_launch(void* const* d_in, const int* in_sizes, int n_in,
                              void* d_out, int out_size)
{
    const float* x    = (const float*)d_in[0];
    const float* q_w  = (const float*)d_in[1];
    const float* q_b  = (const float*)d_in[2];
    const float* q_a  = (const float*)d_in[3];
    const float* q_g  = (const float*)d_in[4];
    const float* q_be = (const float*)d_in[5];
    const float* k_w  = (const float*)d_in[6];
    const float* k_b  = (const float*)d_in[7];
    const float* k_a  = (const float*)d_in[8];
    const float* k_g  = (const float*)d_in[9];
    const float* k_be = (const float*)d_in[10];
    const float* v_w  = (const float*)d_in[11];
    const float* v_b  = (const float*)d_in[12];
    const float* v_a  = (const float*)d_in[13];
    const float* v_g  = (const float*)d_in[14];
    const float* v_be = (const float*)d_in[15];
    const float* l_w  = (const float*)d_in[16];
    const float* l_b  = (const float*)d_in[17];
    const float* l_a  = (const float*)d_in[18];
    const float* l_g  = (const float*)d_in[19];
    const float* l_be = (const float*)d_in[20];
    float* out = (float*)d_out;

    // 4 stages * (128+128) rows * 40 halves * 2B = 81920
    const int SMEM_BYTES = 4 * 2 * 128 * 40 * 2;
    cudaFuncSetAttribute(gemm_qk_h, cudaFuncAttributeMaxDynamicSharedMemorySize, SMEM_BYTES);
    cudaFuncSetAttribute(gemm_pv_h, cudaFuncAttributeMaxDynamicSharedMemorySize, SMEM_BYTES);

    qkv_kernel<<<Bb * Tt, 256>>>(x,
        q_w, q_b, q_a, q_g, q_be,
        k_w, k_b, k_a, k_g, k_be,
        v_w, v_b, v_a, v_g, v_be);

    transV_kernel<<<dim3(DV / 32, Tp / 32, HB), 256>>>();

    gemm_qk_h<<<dim3(8, 8, HB), 256, SMEM_BYTES>>>();

    softmax_kernel<<<HB * Tt, 256>>>();

    gemm_pv_h<<<dim3(8, 8, HB), 256, SMEM_BYTES>>>();

    out_kernel<<<Bb * Tt, 256>>>(x, l_w, l_b, l_a, l_g, l_be, out);
}

// round 16
// speedup vs baseline: 1.0366x; 1.0366x over previous
#include <cuda_runtime.h>
#include <cuda_fp16.h>
#include <math.h>
#include <stdint.h>

#define EPSV 1e-5f
constexpr int Bb=8, Cc=64, Tt=1000, Ff=64, Hh=4, HSs=4, CVv=16;
constexpr int Dd=HSs*Ff, DV=CVv*Ff, HB=Hh*Bb, Tp=1024;

// zero-initialized device scratch (padded tails stay zero forever)
__device__ __half g_Qh [HB * Tp * Dd];   // [t][d]
__device__ __half g_Kh [HB * Tp * Dd];   // [s][d]
__device__ __half g_Vh [HB * Tp * DV];   // [s][n]
__device__ __half g_Vth[HB * DV * Tp];   // [n][s]
__device__ float  g_P  [HB * Tp * Tp];   // scores [t][s] float
__device__ __half g_Ph [HB * Tp * Tp];   // probs  [t][s] half (pads stay 0)
__device__ __half g_Ah [HB * Tp * DV];   // attention out [t][n] HALF

// ---------------- helpers ----------------
__device__ __forceinline__ uint32_t smem_u32(const void* p) {
    uint32_t a;
    asm("{ .reg .u64 t; cvta.to.shared.u64 t, %1; cvt.u32.u64 %0, t; }" : "=r"(a) : "l"(p));
    return a;
}
#define LDM4(r0,r1,r2,r3,addr) \
    asm volatile("ldmatrix.sync.aligned.m8n8.x4.shared.b16 {%0,%1,%2,%3}, [%4];" \
        : "=r"(r0),"=r"(r1),"=r"(r2),"=r"(r3) : "r"(addr))
#define CPASYNC16(sdst, gsrc) \
    asm volatile("cp.async.cg.shared.global [%0], [%1], 16;" :: "r"(sdst), "l"(gsrc))
#define CPCOMMIT() asm volatile("cp.async.commit_group;")
#define CPWAIT1()  asm volatile("cp.async.wait_group 1;")

__device__ __forceinline__ void mma_f16(float* c, const uint32_t* a, const uint32_t* b) {
    asm volatile(
        "mma.sync.aligned.m16n8k16.row.col.f32.f16.f16.f32 "
        "{%0,%1,%2,%3}, {%4,%5,%6,%7}, {%8,%9}, {%0,%1,%2,%3};"
        : "+f"(c[0]), "+f"(c[1]), "+f"(c[2]), "+f"(c[3])
        : "r"(a[0]), "r"(a[1]), "r"(a[2]), "r"(a[3]), "r"(b[0]), "r"(b[1]));
}
__device__ __forceinline__ void group_reduce64(float& s, float& ss, int tid,
                                               float* reds, float* redss) {
    #pragma unroll
    for (int o = 16; o > 0; o >>= 1) {
        s  += __shfl_xor_sync(0xffffffffu, s,  o);
        ss += __shfl_xor_sync(0xffffffffu, ss, o);
    }
    if ((tid & 31) == 0) { reds[tid >> 5] = s; redss[tid >> 5] = ss; }
    __syncthreads();
    int h = tid >> 6;
    s  = reds[2 * h]  + reds[2 * h + 1];
    ss = redss[2 * h] + redss[2 * h + 1];
    __syncthreads();
}

// C-store helpers (float or half output)
__device__ __forceinline__ void storeC2(float* Cg, size_t idx, float a, float b) {
    *(float2*)&Cg[idx] = make_float2(a, b);
}
__device__ __forceinline__ void storeC2(__half* Cg, size_t idx, float a, float b) {
    *(__half2*)&Cg[idx] = __floats2half2_rn(a, b);
}

// ---------------- Kernel 1: QKV proj + PReLU + ChanFreqNorm (half out) -----
__global__ void __launch_bounds__(256) qkv_kernel(
    const float* __restrict__ x,
    const float* __restrict__ qw, const float* __restrict__ qb,
    const float* __restrict__ qa, const float* __restrict__ qg, const float* __restrict__ qbe,
    const float* __restrict__ kw, const float* __restrict__ kb,
    const float* __restrict__ ka, const float* __restrict__ kg, const float* __restrict__ kbe,
    const float* __restrict__ vw, const float* __restrict__ vb,
    const float* __restrict__ va, const float* __restrict__ vg, const float* __restrict__ vbe)
{
    __shared__ float xs[Cc * Ff], qws[Hh*HSs*Cc], kws[Hh*HSs*Cc], vws[Hh*CVv*Cc];
    __shared__ float reds[8], redss[8];
    int bid = blockIdx.x, b = bid / Tt, t = bid % Tt, tid = threadIdx.x;

    for (int i = tid; i < Cc * Ff; i += 256) {
        int c = i >> 6, f = i & 63;
        xs[i] = x[(((size_t)b * Cc + c) * Tt + t) * Ff + f];
    }
    for (int i = tid; i < Hh*HSs*Cc; i += 256) { qws[i] = qw[i]; kws[i] = kw[i]; }
    for (int i = tid; i < Hh*CVv*Cc; i += 256) vws[i] = vw[i];
    __syncthreads();

    int h = tid >> 6, f = tid & 63;
    float qv[HSs], kv[HSs], vv[CVv];
    #pragma unroll
    for (int i = 0; i < HSs; i++) { qv[i] = 0.f; kv[i] = 0.f; }
    #pragma unroll
    for (int i = 0; i < CVv; i++) vv[i] = 0.f;

    for (int c = 0; c < Cc; c++) {
        float xv = xs[c * Ff + f];
        #pragma unroll
        for (int i = 0; i < HSs; i++) {
            qv[i] = fmaf(qws[(h*HSs+i)*Cc + c], xv, qv[i]);
            kv[i] = fmaf(kws[(h*HSs+i)*Cc + c], xv, kv[i]);
        }
        #pragma unroll
        for (int i = 0; i < CVv; i++)
            vv[i] = fmaf(vws[(h*CVv+i)*Cc + c], xv, vv[i]);
    }
    int hb = h * Bb + b;
    { // Q
        float al = qa[h], s = 0.f, ss = 0.f;
        #pragma unroll
        for (int i = 0; i < HSs; i++) {
            float y = qv[i] + qb[h*HSs+i]; y = y > 0.f ? y : al * y;
            qv[i] = y; s += y; ss += y * y;
        }
        group_reduce64(s, ss, tid, reds, redss);
        float mu = s / (HSs*Ff), var = ss / (HSs*Ff) - mu*mu;
        float inv = 1.f / (sqrtf(fmaxf(var, 0.f)) + EPSV);
        size_t base = ((size_t)hb * Tp + t) * Dd;
        #pragma unroll
        for (int i = 0; i < HSs; i++) {
            int gi = (h*HSs+i)*Ff + f;
            g_Qh[base + i*Ff + f] = __float2half((qv[i]-mu)*inv*qg[gi] + qbe[gi]);
        }
    }
    { // K
        float al = ka[h], s = 0.f, ss = 0.f;
        #pragma unroll
        for (int i = 0; i < HSs; i++) {
            float y = kv[i] + kb[h*HSs+i]; y = y > 0.f ? y : al * y;
            kv[i] = y; s += y; ss += y * y;
        }
        group_reduce64(s, ss, tid, reds, redss);
        float mu = s / (HSs*Ff), var = ss / (HSs*Ff) - mu*mu;
        float inv = 1.f / (sqrtf(fmaxf(var, 0.f)) + EPSV);
        size_t base = ((size_t)hb * Tp + t) * Dd;
        #pragma unroll
        for (int i = 0; i < HSs; i++) {
            int gi = (h*HSs+i)*Ff + f;
            g_Kh[base + i*Ff + f] = __float2half((kv[i]-mu)*inv*kg[gi] + kbe[gi]);
        }
    }
    { // V
        float al = va[h], s = 0.f, ss = 0.f;
        #pragma unroll
        for (int i = 0; i < CVv; i++) {
            float y = vv[i] + vb[h*CVv+i]; y = y > 0.f ? y : al * y;
            vv[i] = y; s += y; ss += y * y;
        }
        group_reduce64(s, ss, tid, reds, redss);
        float mu = s / (CVv*Ff), var = ss / (CVv*Ff) - mu*mu;
        float inv = 1.f / (sqrtf(fmaxf(var, 0.f)) + EPSV);
        size_t base = ((size_t)hb * Tp + t) * DV;
        #pragma unroll
        for (int i = 0; i < CVv; i++) {
            int gi = (h*CVv+i)*Ff + f;
            g_Vh[base + i*Ff + f] = __float2half((vv[i]-mu)*inv*vg[gi] + vbe[gi]);
        }
    }
}

// ---------------- Kernel 2: transpose Vh [s][n] -> Vth [n][s] (half) -------
__global__ void __launch_bounds__(256) transV_kernel()
{
    __shared__ __half tile[32][34];
    int hb = blockIdx.z, t0 = blockIdx.y * 32, n0 = blockIdx.x * 32;
    int tx = threadIdx.x & 31, ty = threadIdx.x >> 5;
    const __half* __restrict__ src = g_Vh  + (size_t)hb * Tp * DV;
    __half* __restrict__       dst = g_Vth + (size_t)hb * DV * Tp;
    #pragma unroll
    for (int j = 0; j < 4; j++)
        tile[ty + 8*j][tx] = src[(size_t)(t0 + ty + 8*j) * DV + n0 + tx];
    __syncthreads();
    #pragma unroll
    for (int j = 0; j < 4; j++)
        dst[(size_t)(n0 + ty + 8*j) * Tp + t0 + tx] = tile[tx][ty + 8*j];
}

// ---------------- fp16 GEMM 128x128: C[m][n] = sum_k A[m][k]*B[n][k] -------
// Round-9-proven: BK=32, 3-stage cp.async, non-trans ldmatrix,
// smem row stride 40 halves (80B) -> conflict-free, zero swizzle ALU.
template<typename CT, int LDA, int LDB, int KT>
__device__ __forceinline__ void gemm_h16(const __half* __restrict__ Ag,
                                         const __half* __restrict__ Bg,
                                         CT* __restrict__ Cg, float scale)
{
    extern __shared__ __half sh[];
    const int RS  = 40;          // halves per smem row
    const int STG = 128 * RS;    // halves per stage per operand
    __half* sA = sh;             // [3][STG]
    __half* sB = sh + 3 * STG;

    int tid = threadIdx.x, lane = tid & 31, w = tid >> 5;
    int m0 = blockIdx.y * 128, n0 = blockIdx.x * 128;
    int wm = (w & 1) * 64, wn = (w >> 1) * 32;
    int r = lane >> 2, cq = lane & 3;
    int g = lane >> 3, rw = lane & 7;

    uint32_t sA_u = smem_u32(sA), sB_u = smem_u32(sB);

    // cp.async: thread -> row lr (0..127), 32B (two 16B chunks) at c0
    int lr = tid >> 1, c0 = (tid & 1) * 16;       // c0 in halves
    uint32_t sAd = sA_u + (uint32_t)(lr * RS + c0) * 2;
    uint32_t sBd = sB_u + (uint32_t)(lr * RS + c0) * 2;
    const __half* Asrc = Ag + (size_t)(m0 + lr) * LDA + c0;
    const __half* Bsrc = Bg + (size_t)(n0 + lr) * LDB + c0;

    auto LOAD = [&](int kt) {
        uint32_t so = (uint32_t)(kt % 3) * STG * 2;
        CPASYNC16(sAd + so,      Asrc + kt * 32);
        CPASYNC16(sAd + so + 16, Asrc + kt * 32 + 8);
        CPASYNC16(sBd + so,      Bsrc + kt * 32);
        CPASYNC16(sBd + so + 16, Bsrc + kt * 32 + 8);
        CPCOMMIT();
    };

    // ldmatrix lane offset (bytes): row = (g&1)*8 + rw, k-chunk = (g>>1)
    uint32_t lofs = (uint32_t)(((g & 1) * 8 + rw) * (RS * 2) + (g >> 1) * 16);

    float acc[4][4][4];
    #pragma unroll
    for (int i = 0; i < 4; i++)
        #pragma unroll
        for (int j = 0; j < 4; j++)
            #pragma unroll
            for (int q = 0; q < 4; q++) acc[i][j][q] = 0.f;

    LOAD(0); LOAD(1);

    for (int kt = 0; kt < KT; kt++) {
        CPWAIT1();
        __syncthreads();
        uint32_t so = (uint32_t)(kt % 3) * STG * 2;
        uint32_t bufA = sA_u + so + lofs;
        uint32_t bufB = sB_u + so + lofs;
        #pragma unroll
        for (int ks = 0; ks < 2; ks++) {
            uint32_t af[4][4], bf[4][2];
            #pragma unroll
            for (int mi = 0; mi < 4; mi++)
                LDM4(af[mi][0], af[mi][1], af[mi][2], af[mi][3],
                     bufA + (uint32_t)((wm + mi * 16) * (RS * 2) + ks * 32));
            #pragma unroll
            for (int nj = 0; nj < 2; nj++) {
                uint32_t q0, q1, q2, q3;
                LDM4(q0, q1, q2, q3,
                     bufB + (uint32_t)((wn + nj * 16) * (RS * 2) + ks * 32));
                bf[nj*2][0]   = q0;  bf[nj*2][1]   = q2;
                bf[nj*2+1][0] = q1;  bf[nj*2+1][1] = q3;
            }
            #pragma unroll
            for (int mi = 0; mi < 4; mi++)
                #pragma unroll
                for (int ni = 0; ni < 4; ni++)
                    mma_f16(acc[mi][ni], af[mi], bf[ni]);
        }
        // commit every iteration so wait_group 1 drains the tail correctly
        if (kt + 2 < KT) LOAD(kt + 2);
        else CPCOMMIT();
    }

    #pragma unroll
    for (int mi = 0; mi < 4; mi++)
        #pragma unroll
        for (int ni = 0; ni < 4; ni++) {
            int row = m0 + wm + mi * 16 + r;
            int col = n0 + wn + ni * 8 + 2 * cq;
            storeC2(Cg, (size_t)row * 1024 + col,
                    acc[mi][ni][0] * scale, acc[mi][ni][1] * scale);
            storeC2(Cg, (size_t)(row + 8) * 1024 + col,
                    acc[mi][ni][2] * scale, acc[mi][ni][3] * scale);
        }
}

// S[t][s] = sum_d Q[t][d] * K[s][d], scaled -> float
__global__ void __launch_bounds__(256, 2) gemm_qk_h()
{
    int hb = blockIdx.z;
    gemm_h16<float, Dd, Dd, Dd/32>(g_Qh + (size_t)hb * Tp * Dd,
                                   g_Kh + (size_t)hb * Tp * Dd,
                                   g_P  + (size_t)hb * Tp * Tp, 0.0625f);
}
// A[t][n] = sum_s P[t][s] * Vt[n][s] -> half
__global__ void __launch_bounds__(256, 2) gemm_pv_h()
{
    int hb = blockIdx.z;
    gemm_h16<__half, Tp, Tp, Tp/32>(g_Ph  + (size_t)hb * Tp * Tp,
                                    g_Vth + (size_t)hb * DV * Tp,
                                    g_Ah  + (size_t)hb * Tp * DV, 1.0f);
}

// ---------------- Kernel 3: row softmax S(float) -> P(half), zero pads -----
__global__ void __launch_bounds__(256) softmax_kernel()
{
    __shared__ float red[8];
    int hb = blockIdx.x / Tt, mrow = blockIdx.x % Tt;
    const float* __restrict__ p = g_P  + ((size_t)hb * Tp + mrow) * Tp;
    __half* __restrict__      o = g_Ph + ((size_t)hb * Tp + mrow) * Tp;
    int tid = threadIdx.x;

    float v[4];
    int cnt = 0;
    float m = -1e30f;
    for (int i = tid; i < Tt; i += 256) { v[cnt] = p[i]; m = fmaxf(m, v[cnt]); cnt++; }
    #pragma unroll
    for (int off = 16; off > 0; off >>= 1) m = fmaxf(m, __shfl_xor_sync(0xffffffffu, m, off));
    if ((tid & 31) == 0) red[tid >> 5] = m;
    __syncthreads();
    m = red[0];
    #pragma unroll
    for (int wv = 1; wv < 8; wv++) m = fmaxf(m, red[wv]);
    __syncthreads();

    float s = 0.f;
    for (int i = 0; i < cnt; i++) { v[i] = __expf(v[i] - m); s += v[i]; }
    #pragma unroll
    for (int off = 16; off > 0; off >>= 1) s += __shfl_xor_sync(0xffffffffu, s, off);
    if ((tid & 31) == 0) red[tid >> 5] = s;
    __syncthreads();
    s = 0.f;
    #pragma unroll
    for (int wv = 0; wv < 8; wv++) s += red[wv];

    float inv = 1.f / s;
    cnt = 0;
    for (int i = tid; i < Tt; i += 256) { o[i] = __float2half(v[cnt] * inv); cnt++; }
    for (int i = Tt + tid; i < Tp; i += 256) o[i] = __float2half(0.f);
}

// ---------------- Kernel 5: out proj + PReLU + ChanFreqNorm + residual -----
__global__ void __launch_bounds__(256) out_kernel(
    const float* __restrict__ x,
    const float* __restrict__ lw, const float* __restrict__ lb,
    const float* __restrict__ la, const float* __restrict__ lg,
    const float* __restrict__ lbe, float* __restrict__ out)
{
    __shared__ float xs[Cc * Ff], lws[Cc * Cc];
    __shared__ float reds[8], redss[8];
    int bid = blockIdx.x, b = bid / Tt, t = bid % Tt, tid = threadIdx.x;

    for (int h = 0; h < Hh; h++) {
        size_t base = ((size_t)(h * Bb + b) * Tp + t) * DV;
        for (int i = tid; i < DV; i += 256)
            xs[h * DV + i] = __half2float(g_Ah[base + i]);
    }
    for (int i = tid; i < Cc * Cc; i += 256) lws[i] = lw[i];
    __syncthreads();

    int f = tid & 63, co = tid >> 6;
    float alpha = la[0];
    float yv[16];
    #pragma unroll
    for (int j = 0; j < 16; j++) yv[j] = lb[co * 16 + j];
    for (int ci = 0; ci < Cc; ci++) {
        float xv = xs[ci * Ff + f];
        #pragma unroll
        for (int j = 0; j < 16; j++)
            yv[j] = fmaf(lws[(co * 16 + j) * Cc + ci], xv, yv[j]);
    }
    float s = 0.f, ss = 0.f;
    #pragma unroll
    for (int j = 0; j < 16; j++) {
        float y = yv[j]; y = y > 0.f ? y : alpha * y;
        yv[j] = y; s += y; ss += y * y;
    }
    #pragma unroll
    for (int o = 16; o > 0; o >>= 1) {
        s  += __shfl_xor_sync(0xffffffffu, s,  o);
        ss += __shfl_xor_sync(0xffffffffu, ss, o);
    }
    if ((tid & 31) == 0) { reds[tid >> 5] = s; redss[tid >> 5] = ss; }
    __syncthreads();
    s = 0.f; ss = 0.f;
    #pragma unroll
    for (int wv = 0; wv < 8; wv++) { s += reds[wv]; ss += redss[wv]; }

    float mu  = s * (1.f / 4096.f);
    float var = ss * (1.f / 4096.f) - mu * mu;
    float inv = 1.f / (sqrtf(fmaxf(var, 0.f)) + EPSV);
    #pragma unroll
    for (int j = 0; j < 16; j++) {
        int c = co * 16 + j;
        size_t oi = (((size_t)b * Cc + c) * Tt + t) * Ff + f;
        out[oi] = (yv[j] - mu) * inv * lg[c * Ff + f] + lbe[c * Ff + f] + x[oi];
    }
}

// ---------------------------------------------------------------------------
extern "C" void kernel_launch(void* const* d_in, const int* in_sizes, int n_in,
                              void* d_out, int out_size)
{
    const float* x    = (const float*)d_in[0];
    const float* q_w  = (const float*)d_in[1];
    const float* q_b  = (const float*)d_in[2];
    const float* q_a  = (const float*)d_in[3];
    const float* q_g  = (const float*)d_in[4];
    const float* q_be = (const float*)d_in[5];
    const float* k_w  = (const float*)d_in[6];
    const float* k_b  = (const float*)d_in[7];
    const float* k_a  = (const float*)d_in[8];
    const float* k_g  = (const float*)d_in[9];
    const float* k_be = (const float*)d_in[10];
    const float* v_w  = (const float*)d_in[11];
    const float* v_b  = (const float*)d_in[12];
    const float* v_a  = (const float*)d_in[13];
    const float* v_g  = (const float*)d_in[14];
    const float* v_be = (const float*)d_in[15];
    const float* l_w  = (const float*)d_in[16];
    const float* l_b  = (const float*)d_in[17];
    const float* l_a  = (const float*)d_in[18];
    const float* l_g  = (const float*)d_in[19];
    const float* l_be = (const float*)d_in[20];
    float* out = (float*)d_out;

    // 3 stages * 2 operands * 128 rows * 40 halves * 2B = 61440
    const int SMEM_BYTES = 3 * 2 * 128 * 40 * 2;
    cudaFuncSetAttribute(gemm_qk_h, cudaFuncAttributeMaxDynamicSharedMemorySize, SMEM_BYTES);
    cudaFuncSetAttribute(gemm_pv_h, cudaFuncAttributeMaxDynamicSharedMemorySize, SMEM_BYTES);

    qkv_kernel<<<Bb * Tt, 256>>>(x,
        q_w, q_b, q_a, q_g, q_be,
        k_w, k_b, k_a, k_g, k_be,
        v_w, v_b, v_a, v_g, v_be);

    transV_kernel<<<dim3(DV / 32, Tp / 32, HB), 256>>>();

    gemm_qk_h<<<dim3(8, 8, HB), 256, SMEM_BYTES>>>();

    softmax_kernel<<<HB * Tt, 256>>>();

    gemm_pv_h<<<dim3(8, 8, HB), 256, SMEM_BYTES>>>();

    out_kernel<<<Bb * Tt, 256>>>(x, l_w, l_b, l_a, l_g, l_be, out);
}